// round 13
// baseline (speedup 1.0000x reference)
#include <cuda_runtime.h>
#include <cuda_fp16.h>
#include <cstdint>

#define NB 8
#define CC 256
#define CQh 128
#define NN 4096
#define RSB 80          // smem row stride bytes -> conflict-free fragment LDS
#define TILEB 10240     // 128 rows * 80B

// ---------------- scratch (device globals) ----------------------------------
__device__ __half g_xT [(size_t)NB*NN*CC];     // [b][m][c]
__device__ __half g_qk [(size_t)NB*NN*CC];     // [b][m][o] o<128: q*log2e, else k
__device__ __half g_v  [(size_t)NB*CC*NN];     // [b][c][m]
__device__ __half g_E  [(size_t)NB*NN*NN];     // [b][m][n] = exp(S)  268MB
__device__ float  g_csum[NB*NN];               // column sums (atomic)
__device__ __half g_rcph[NB*NN];               // fp16(256/colsum)
__device__ __half g_Wqk[2*CQh*CC];
__device__ __half g_Wv [CC*CC];
__device__ float  g_bias[512];                 // q:0-127 (x log2e) k:128-255 v:256-511

// ---------------- helpers ----------------------------------------------------
__device__ __forceinline__ uint32_t smem_u32(const void* p){
    uint32_t a;
    asm("{ .reg .u64 t; cvta.to.shared.u64 t, %1; cvt.u32.u64 %0, t; }" : "=r"(a) : "l"(p));
    return a;
}
// fma-pipe 2^t (scores pre-scaled by log2e); degree-5, rel err ~1.6e-4
__device__ __forceinline__ float fexp2(float t){
    t = fmaxf(t, -80.f);
    float fi = floorf(t);
    float f = t - fi;
    float p = 1.33335581e-3f;
    p = fmaf(p, f, 9.61812911e-3f);
    p = fmaf(p, f, 5.55041087e-2f);
    p = fmaf(p, f, 2.40226507e-1f);
    p = fmaf(p, f, 6.93147181e-1f);
    p = fmaf(p, f, 1.0f);
    return __int_as_float(__float_as_int(p) + ((int)fi << 23));
}
__device__ __forceinline__ uint32_t pack_h2_sat(float lo, float hi){
    uint32_t r;
    asm("cvt.rn.satfinite.f16x2.f32 %0, %1, %2;" : "=r"(r) : "f"(hi), "f"(lo));
    return r;
}

#define MMA_H16(acc, a, b)                                                     \
    asm volatile("mma.sync.aligned.m16n8k16.row.col.f32.f16.f16.f32 "          \
        "{%0,%1,%2,%3}, {%4,%5,%6,%7}, {%8,%9}, {%0,%1,%2,%3};"                \
        : "+f"((acc)[0]), "+f"((acc)[1]), "+f"((acc)[2]), "+f"((acc)[3])       \
        : "r"((a)[0]), "r"((a)[1]), "r"((a)[2]), "r"((a)[3]),                  \
          "r"((b)[0]), "r"((b)[1]))

// fp16-accumulator variant: two packed f16x2 C regs
#define MMA_H16ACC(acc2, a, b)                                                 \
    asm volatile("mma.sync.aligned.m16n8k16.row.col.f16.f16.f16.f16 "          \
        "{%0,%1}, {%2,%3,%4,%5}, {%6,%7}, {%0,%1};"                            \
        : "+r"((acc2)[0]), "+r"((acc2)[1])                                     \
        : "r"((a)[0]), "r"((a)[1]), "r"((a)[2]), "r"((a)[3]),                  \
          "r"((b)[0]), "r"((b)[1]))

// ---------------- fragment compute (one 32-deep K chunk, scalar LDS) ---------
__device__ __forceinline__ void compute_chunk(uint32_t sA, uint32_t sB, int buf,
                                              int lane, int wm, int wn, float acc[4][4][4])
{
    uint32_t aA = sA + buf*TILEB + (wm*64 + (lane>>2))*RSB + (lane&3)*4;
    uint32_t aB = sB + buf*TILEB + (wn*32 + (lane>>2))*RSB + (lane&3)*4;
    #pragma unroll
    for (int ks = 0; ks < 2; ks++){
        uint32_t a[4][4], b[4][2];
        #pragma unroll
        for (int mi = 0; mi < 4; mi++){
            uint32_t base = aA + mi*16*RSB + ks*32;
            asm volatile("ld.shared.b32 %0, [%1];" : "=r"(a[mi][0]) : "r"(base));
            asm volatile("ld.shared.b32 %0, [%1];" : "=r"(a[mi][1]) : "r"(base + 8*RSB));
            asm volatile("ld.shared.b32 %0, [%1];" : "=r"(a[mi][2]) : "r"(base + 16));
            asm volatile("ld.shared.b32 %0, [%1];" : "=r"(a[mi][3]) : "r"(base + 8*RSB + 16));
        }
        #pragma unroll
        for (int nj = 0; nj < 4; nj++){
            uint32_t base = aB + nj*8*RSB + ks*32;
            asm volatile("ld.shared.b32 %0, [%1];" : "=r"(b[nj][0]) : "r"(base));
            asm volatile("ld.shared.b32 %0, [%1];" : "=r"(b[nj][1]) : "r"(base + 16));
        }
        #pragma unroll
        for (int mi = 0; mi < 4; mi++)
            #pragma unroll
            for (int nj = 0; nj < 4; nj++)
                MMA_H16(acc[mi][nj], a[mi], b[nj]);
    }
}

// ---------------- generic fp16 GEMM core (cp.async, ONE sync per chunk) ------
__device__ __forceinline__ void ldchunk(uint32_t sA, uint32_t sB,
    const __half* __restrict__ A, int lda, const __half* __restrict__ B, int ldb,
    int kt, int buf, int tid)
{
    const __half* Ak = A + kt*32;
    const __half* Bk = B + kt*32;
    #pragma unroll
    for (int r = 0; r < 2; r++){
        int t = tid + r*256;
        int row = t >> 2, seg = t & 3;
        uint32_t off = (uint32_t)(buf*TILEB + row*RSB + seg*16);
        asm volatile("cp.async.ca.shared.global [%0], [%1], 16;"
            :: "r"(sA + off), "l"(Ak + (size_t)row*lda + seg*8) : "memory");
        asm volatile("cp.async.ca.shared.global [%0], [%1], 16;"
            :: "r"(sB + off), "l"(Bk + (size_t)row*ldb + seg*8) : "memory");
    }
    asm volatile("cp.async.commit_group;" ::: "memory");
}

__device__ __forceinline__ void gemm_h16(
    const __half* __restrict__ A, int lda,
    const __half* __restrict__ B, int ldb,
    int K, uint8_t* smp, float acc[4][4][4])
{
    const int tid = threadIdx.x, lane = tid & 31, wid = tid >> 5;
    const int wm = wid & 1, wn = wid >> 1;
    uint32_t sA = smem_u32(smp), sB = sA + 2*TILEB;
    const int KT = K >> 5;

    ldchunk(sA, sB, A, lda, B, ldb, 0, 0, tid);
    for (int kt = 0; kt < KT; kt++){
        int buf = kt & 1;
        asm volatile("cp.async.wait_group 0;" ::: "memory");
        __syncthreads();
        if (kt + 1 < KT)
            ldchunk(sA, sB, A, lda, B, ldb, kt+1, buf^1, tid);
        compute_chunk(sA, sB, buf, lane, wm, wn, acc);
    }
}

#define GEMM_PROLOG                                            \
    __shared__ __align__(128) uint8_t sm[4*TILEB];             \
    const int lane = threadIdx.x & 31, wid = threadIdx.x >> 5; \
    float acc[4][4][4] = {};

// ---------------- prep kernels -----------------------------------------------
__global__ __launch_bounds__(256) void prep_w(
    const float* __restrict__ Wq, const float* __restrict__ bq,
    const float* __restrict__ Wk, const float* __restrict__ bk,
    const float* __restrict__ Wv, const float* __restrict__ bv)
{
    const float L2E = 1.44269504f;
    int i = blockIdx.x*256 + threadIdx.x;          // 65536 threads
    if (i < 32768) { g_Wqk[i] = __float2half_rn(Wq[i]*L2E); g_Wqk[32768 + i] = __float2half_rn(Wk[i]); }
    g_Wv[i] = __float2half_rn(Wv[i]);
    if (i < NB*NN) g_csum[i] = 0.f;                // zero colsum accumulators each replay
    if (i < 128) { g_bias[i] = bq[i]*L2E; g_bias[128 + i] = bk[i]; }
    if (i < 256) g_bias[256 + i] = bv[i];
}

__global__ __launch_bounds__(256) void prep_xT(const float* __restrict__ x)
{
    __shared__ float t[32][33];
    int b = blockIdx.z, m0 = blockIdx.x*32, c0 = blockIdx.y*32;
    int tx = threadIdx.x, ty = threadIdx.y;        // (32, 8)
    #pragma unroll
    for (int j = 0; j < 4; j++)
        t[ty + j*8][tx] = x[((size_t)b*CC + c0 + ty + j*8)*NN + m0 + tx];
    __syncthreads();
    #pragma unroll
    for (int j = 0; j < 4; j++)
        g_xT[((size_t)b*NN + m0 + ty + j*8)*CC + c0 + tx] = __float2half_rn(t[tx][ty + j*8]);
}

// ---------------- merged projection kernel -----------------------------------
__global__ __launch_bounds__(256, 2) void k_proj()
{
    GEMM_PROLOG
    int b = blockIdx.z, m0 = blockIdx.x*128;
    const __half* xb = g_xT + ((size_t)b*NN + m0)*CC;
    if (blockIdx.y < 2){
        int o0 = blockIdx.y*128;
        gemm_h16(xb, CC, g_Wqk + (size_t)o0*CC, CC, CC, sm, acc);
        int rb = m0 + (wid & 1)*64 + (lane >> 2);
        int cb = o0 + (wid >> 1)*32 + (lane & 3)*2;
        #pragma unroll
        for (int mi = 0; mi < 4; mi++)
            #pragma unroll
            for (int nj = 0; nj < 4; nj++){
                int r = rb + mi*16, c = cb + nj*8;
                float b0 = g_bias[c], b1 = g_bias[c + 1];
                __half* op = g_qk + ((size_t)b*NN + r)*CC + c;
                *reinterpret_cast<uint32_t*>(op)        = pack_h2_sat(acc[mi][nj][0] + b0, acc[mi][nj][1] + b1);
                *reinterpret_cast<uint32_t*>(op + 8*CC) = pack_h2_sat(acc[mi][nj][2] + b0, acc[mi][nj][3] + b1);
            }
    } else {
        int c0 = (blockIdx.y - 2)*128;
        gemm_h16(g_Wv + (size_t)c0*CC, CC, xb, CC, CC, sm, acc);
        int rb = c0 + (wid & 1)*64 + (lane >> 2);
        int cb = m0 + (wid >> 1)*32 + (lane & 3)*2;
        #pragma unroll
        for (int mi = 0; mi < 4; mi++)
            #pragma unroll
            for (int nj = 0; nj < 4; nj++){
                int r = rb + mi*16, c = cb + nj*8;
                float b0 = g_bias[256 + r], b1 = g_bias[256 + r + 8];
                __half* op = g_v + ((size_t)b*CC + r)*NN + c;
                *reinterpret_cast<uint32_t*>(op)        = pack_h2_sat(acc[mi][nj][0] + b0, acc[mi][nj][1] + b0);
                *reinterpret_cast<uint32_t*>(op + 8*NN) = pack_h2_sat(acc[mi][nj][2] + b1, acc[mi][nj][3] + b1);
            }
    }
}

// ---------------- scores: 4 warps, 64x64 warp tiles, fp16 accumulators -------
// E[m][n] = 2^(q'[m].k[n]); fused per-column partial sums
__global__ __launch_bounds__(128, 4) void k_scores()
{
    __shared__ __align__(128) uint8_t sm[4*TILEB];
    const int tid = threadIdx.x, lane = tid & 31, wid = tid >> 5;
    const int wm = wid & 1, wn = wid >> 1;        // warps 2(M) x 2(N)
    uint32_t acc[4][8][2] = {};                   // fp16x2 accumulators, 64 regs

    int b = blockIdx.z, m0 = blockIdx.x*128, n0 = blockIdx.y*128;
    const __half* A = g_qk + ((size_t)b*NN + m0)*CC;
    const __half* B = g_qk + ((size_t)b*NN + n0)*CC + CQh;
    uint32_t sA = smem_u32(sm), sB = sA + 2*TILEB;
    const int KT = CQh >> 5;                      // 4

    auto ld128 = [&](int kt, int buf){
        const __half* Ak = A + kt*32;
        const __half* Bk = B + kt*32;
        #pragma unroll
        for (int r = 0; r < 4; r++){
            int t = tid + r*128;
            int row = t >> 2, seg = t & 3;
            uint32_t off = (uint32_t)(buf*TILEB + row*RSB + seg*16);
            asm volatile("cp.async.ca.shared.global [%0], [%1], 16;"
                :: "r"(sA + off), "l"(Ak + (size_t)row*CC + seg*8) : "memory");
            asm volatile("cp.async.ca.shared.global [%0], [%1], 16;"
                :: "r"(sB + off), "l"(Bk + (size_t)row*CC + seg*8) : "memory");
        }
        asm volatile("cp.async.commit_group;" ::: "memory");
    };

    ld128(0, 0);
    for (int kt = 0; kt < KT; kt++){
        int buf = kt & 1;
        asm volatile("cp.async.wait_group 0;" ::: "memory");
        __syncthreads();
        if (kt + 1 < KT) ld128(kt+1, buf^1);
        uint32_t aA = sA + buf*TILEB + (wm*64 + (lane>>2))*RSB + (lane&3)*4;
        uint32_t aB = sB + buf*TILEB + (wn*64 + (lane>>2))*RSB + (lane&3)*4;
        #pragma unroll
        for (int ks = 0; ks < 2; ks++){
            uint32_t a[4][4], bfr[8][2];
            #pragma unroll
            for (int mi = 0; mi < 4; mi++){
                uint32_t base = aA + mi*16*RSB + ks*32;
                asm volatile("ld.shared.b32 %0, [%1];" : "=r"(a[mi][0]) : "r"(base));
                asm volatile("ld.shared.b32 %0, [%1];" : "=r"(a[mi][1]) : "r"(base + 8*RSB));
                asm volatile("ld.shared.b32 %0, [%1];" : "=r"(a[mi][2]) : "r"(base + 16));
                asm volatile("ld.shared.b32 %0, [%1];" : "=r"(a[mi][3]) : "r"(base + 8*RSB + 16));
            }
            #pragma unroll
            for (int nj = 0; nj < 8; nj++){
                uint32_t base = aB + nj*8*RSB + ks*32;
                asm volatile("ld.shared.b32 %0, [%1];" : "=r"(bfr[nj][0]) : "r"(base));
                asm volatile("ld.shared.b32 %0, [%1];" : "=r"(bfr[nj][1]) : "r"(base + 16));
            }
            #pragma unroll
            for (int mi = 0; mi < 4; mi++)
                #pragma unroll
                for (int nj = 0; nj < 8; nj++)
                    MMA_H16ACC(acc[mi][nj], a[mi], bfr[nj]);
        }
    }

    // epilogue: exp2 + E store + fused column sums
    int rb = m0 + wm*64 + (lane >> 2);
    int cb = n0 + wn*64 + (lane & 3)*2;
    float cs[8][2];
    #pragma unroll
    for (int nj = 0; nj < 8; nj++){ cs[nj][0] = 0.f; cs[nj][1] = 0.f; }
    #pragma unroll
    for (int mi = 0; mi < 4; mi++)
        #pragma unroll
        for (int nj = 0; nj < 8; nj++){
            __half2 h0 = *reinterpret_cast<__half2*>(&acc[mi][nj][0]);
            __half2 h1 = *reinterpret_cast<__half2*>(&acc[mi][nj][1]);
            float e0 = fexp2(__low2float(h0)), e1 = fexp2(__high2float(h0));
            float e2 = fexp2(__low2float(h1)), e3 = fexp2(__high2float(h1));
            cs[nj][0] += e0 + e2;
            cs[nj][1] += e1 + e3;
            int r = rb + mi*16, c = cb + nj*8;
            __half* op = g_E + ((size_t)b*NN + r)*NN + c;
            *reinterpret_cast<uint32_t*>(op)        = pack_h2_sat(e0, e1);
            *reinterpret_cast<uint32_t*>(op + 8*NN) = pack_h2_sat(e2, e3);
        }
    #pragma unroll
    for (int nj = 0; nj < 8; nj++)
        #pragma unroll
        for (int j = 0; j < 2; j++){
            float v = cs[nj][j];
            v += __shfl_down_sync(0xFFFFFFFFu, v, 4);
            v += __shfl_down_sync(0xFFFFFFFFu, v, 8);
            v += __shfl_down_sync(0xFFFFFFFFu, v, 16);
            cs[nj][j] = v;
        }
    if (lane < 4){
        #pragma unroll
        for (int nj = 0; nj < 8; nj++)
            #pragma unroll
            for (int j = 0; j < 2; j++)
                atomicAdd(&g_csum[b*NN + n0 + wn*64 + lane*2 + nj*8 + j], cs[nj][j]);
    }
}

__global__ __launch_bounds__(256) void k_rcp()
{
    int i = blockIdx.x*256 + threadIdx.x;          // < NB*NN
    g_rcph[i] = __float2half_rn(256.0f / g_csum[i]);
}

// ---------------- output GEMM: P = E * rcp_h (HMUL2) in B loader --------------
// out[c][m] = sum_n v[c][n] * P[m][n];  y = (gamma/256)*out + x
__global__ __launch_bounds__(256, 2) void k_out(
    const float* __restrict__ x, const float* __restrict__ gamma, float* __restrict__ y)
{
    __shared__ __align__(128) uint8_t sm[4*TILEB];
    const int tid = threadIdx.x, lane = tid & 31, wid = tid >> 5;
    const int wm = wid & 1, wn = wid >> 1;
    float acc[4][4][4] = {};
    int b = blockIdx.z, m0 = blockIdx.x*128, c0 = blockIdx.y*128;
    const __half* A = g_v + ((size_t)b*CC + c0)*NN;
    const __half* E = g_E + ((size_t)b*NN + m0)*NN;
    const __half* rcph = g_rcph + b*NN;
    uint32_t sA = smem_u32(sm), sB = sA + 2*TILEB;
    const int KT = NN >> 5;     // 128

    auto cpA = [&](int kt, int buf){
        const __half* Ak = A + kt*32;
        #pragma unroll
        for (int r = 0; r < 2; r++){
            int t = tid + r*256; int row = t>>2, seg = t&3;
            uint32_t off = (uint32_t)(buf*TILEB + row*RSB + seg*16);
            asm volatile("cp.async.ca.shared.global [%0], [%1], 16;"
                :: "r"(sA + off), "l"(Ak + (size_t)row*NN + seg*8) : "memory");
        }
        asm volatile("cp.async.commit_group;" ::: "memory");
    };
    auto ldB = [&](int kt, uint4* v){
        const __half* Ek = E + kt*32;
        #pragma unroll
        for (int r = 0; r < 2; r++){
            int t = tid + r*256; int row = t>>2, seg = t&3;
            v[r] = *reinterpret_cast<const uint4*>(Ek + (size_t)row*NN + seg*8);
        }
    };
    auto stB = [&](int kt, int buf, uint4* v){
        #pragma unroll
        for (int r = 0; r < 2; r++){
            int t = tid + r*256; int row = t>>2, seg = t&3;
            int nb = kt*32 + seg*8;
            uint4 rc = *reinterpret_cast<const uint4*>(rcph + nb);
            const __half2* h  = reinterpret_cast<const __half2*>(&v[r]);
            const __half2* rh = reinterpret_cast<const __half2*>(&rc);
            __half2 o0 = __hmul2(h[0], rh[0]);
            __half2 o1 = __hmul2(h[1], rh[1]);
            __half2 o2 = __hmul2(h[2], rh[2]);
            __half2 o3 = __hmul2(h[3], rh[3]);
            uint4 o;
            o.x = *reinterpret_cast<uint32_t*>(&o0);
            o.y = *reinterpret_cast<uint32_t*>(&o1);
            o.z = *reinterpret_cast<uint32_t*>(&o2);
            o.w = *reinterpret_cast<uint32_t*>(&o3);
            *reinterpret_cast<uint4*>(sm + 2*TILEB + buf*TILEB + row*RSB + seg*16) = o;
        }
    };

    // prologue: chunk 0
    {
        uint4 v[2];
        cpA(0, 0);
        ldB(0, v);
        stB(0, 0, v);
        asm volatile("cp.async.wait_group 0;" ::: "memory");
        __syncthreads();
    }
    for (int kt = 0; kt < KT; kt++){
        int buf = kt & 1;
        uint4 v[2];
        if (kt + 1 < KT){
            cpA(kt+1, buf^1);
            ldB(kt+1, v);
        }
        compute_chunk(sA, sB, buf, lane, wm, wn, acc);
        if (kt + 1 < KT){
            stB(kt+1, buf^1, v);
            asm volatile("cp.async.wait_group 0;" ::: "memory");
        }
        __syncthreads();
    }

    float gm = gamma[0] * 0.00390625f;   // /256 compensates rcp_h scaling
    int rb = c0 + wm*64 + (lane >> 2);
    int cb = m0 + wn*32 + (lane & 3)*2;
    #pragma unroll
    for (int mi = 0; mi < 4; mi++)
        #pragma unroll
        for (int nj = 0; nj < 4; nj++){
            int r = rb + mi*16, c = cb + nj*8;
            size_t p0 = ((size_t)b*CC + r)*NN + c;
            size_t p1 = p0 + (size_t)8*NN;
            float2 x0 = *reinterpret_cast<const float2*>(x + p0);
            float2 x1 = *reinterpret_cast<const float2*>(x + p1);
            *reinterpret_cast<float2*>(y + p0) =
                make_float2(fmaf(gm, acc[mi][nj][0], x0.x), fmaf(gm, acc[mi][nj][1], x0.y));
            *reinterpret_cast<float2*>(y + p1) =
                make_float2(fmaf(gm, acc[mi][nj][2], x1.x), fmaf(gm, acc[mi][nj][3], x1.y));
        }
}

// ---------------- launcher ---------------------------------------------------
extern "C" void kernel_launch(void* const* d_in, const int* in_sizes, int n_in,
                              void* d_out, int out_size)
{
    const float* x     = (const float*)d_in[0];
    const float* Wq    = (const float*)d_in[1];
    const float* bq    = (const float*)d_in[2];
    const float* Wk    = (const float*)d_in[3];
    const float* bk    = (const float*)d_in[4];
    const float* Wv    = (const float*)d_in[5];
    const float* bv    = (const float*)d_in[6];
    const float* gamma = (const float*)d_in[7];
    float* y = (float*)d_out;

    prep_w  <<<256, 256>>>(Wq, bq, Wk, bk, Wv, bv);
    prep_xT <<<dim3(NN/32, CC/32, NB), dim3(32, 8)>>>(x);
    k_proj  <<<dim3(NN/128, 4, NB), 256>>>();
    k_scores<<<dim3(NN/128, NN/128, NB), 128>>>();
    k_rcp   <<<NB*NN/256, 256>>>();
    k_out   <<<dim3(NN/128, CC/128, NB), 256>>>(x, gamma, y);
}

// round 14
// speedup vs baseline: 1.5990x; 1.5990x over previous
#include <cuda_runtime.h>
#include <cuda_fp16.h>
#include <cstdint>

#define NB 8
#define CC 256
#define CQh 128
#define NN 4096
#define RSB 80          // smem row stride bytes -> conflict-free fragment LDS
#define TILEB 10240     // 128 rows * 80B

// ---------------- scratch (device globals) ----------------------------------
__device__ __half g_xT [(size_t)NB*NN*CC];     // [b][m][c]
__device__ __half g_qk [(size_t)NB*NN*CC];     // [b][m][o] o<128: q*log2e, else k
__device__ __half g_v  [(size_t)NB*CC*NN];     // [b][c][m]; scaled by rcp_h in k_vscale
__device__ __half g_E  [(size_t)NB*NN*NN];     // [b][m][n] = exp(S)  268MB
__device__ float  g_csum[NB*NN];               // column sums (atomic)
__device__ __half g_rcph[NB*NN];               // fp16(256/colsum)
__device__ __half g_Wqk[2*CQh*CC];
__device__ __half g_Wv [CC*CC];
__device__ float  g_bias[512];                 // q:0-127 (x log2e) k:128-255 v:256-511

// ---------------- helpers ----------------------------------------------------
__device__ __forceinline__ uint32_t smem_u32(const void* p){
    uint32_t a;
    asm("{ .reg .u64 t; cvta.to.shared.u64 t, %1; cvt.u32.u64 %0, t; }" : "=r"(a) : "l"(p));
    return a;
}
// fma-pipe 2^t (scores pre-scaled by log2e); degree-5, rel err ~1.6e-4
__device__ __forceinline__ float fexp2(float t){
    t = fmaxf(t, -80.f);
    float fi = floorf(t);
    float f = t - fi;
    float p = 1.33335581e-3f;
    p = fmaf(p, f, 9.61812911e-3f);
    p = fmaf(p, f, 5.55041087e-2f);
    p = fmaf(p, f, 2.40226507e-1f);
    p = fmaf(p, f, 6.93147181e-1f);
    p = fmaf(p, f, 1.0f);
    return __int_as_float(__float_as_int(p) + ((int)fi << 23));
}
__device__ __forceinline__ uint32_t pack_h2_sat(float lo, float hi){
    uint32_t r;
    asm("cvt.rn.satfinite.f16x2.f32 %0, %1, %2;" : "=r"(r) : "f"(hi), "f"(lo));
    return r;
}

#define MMA_H16(acc, a, b)                                                     \
    asm volatile("mma.sync.aligned.m16n8k16.row.col.f32.f16.f16.f32 "          \
        "{%0,%1,%2,%3}, {%4,%5,%6,%7}, {%8,%9}, {%0,%1,%2,%3};"                \
        : "+f"((acc)[0]), "+f"((acc)[1]), "+f"((acc)[2]), "+f"((acc)[3])       \
        : "r"((a)[0]), "r"((a)[1]), "r"((a)[2]), "r"((a)[3]),                  \
          "r"((b)[0]), "r"((b)[1]))

// ---------------- fragment compute (one 32-deep K chunk, scalar LDS) ---------
__device__ __forceinline__ void compute_chunk(uint32_t sA, uint32_t sB, int buf,
                                              int lane, int wm, int wn, float acc[4][4][4])
{
    uint32_t aA = sA + buf*TILEB + (wm*64 + (lane>>2))*RSB + (lane&3)*4;
    uint32_t aB = sB + buf*TILEB + (wn*32 + (lane>>2))*RSB + (lane&3)*4;
    #pragma unroll
    for (int ks = 0; ks < 2; ks++){
        uint32_t a[4][4], b[4][2];
        #pragma unroll
        for (int mi = 0; mi < 4; mi++){
            uint32_t base = aA + mi*16*RSB + ks*32;
            asm volatile("ld.shared.b32 %0, [%1];" : "=r"(a[mi][0]) : "r"(base));
            asm volatile("ld.shared.b32 %0, [%1];" : "=r"(a[mi][1]) : "r"(base + 8*RSB));
            asm volatile("ld.shared.b32 %0, [%1];" : "=r"(a[mi][2]) : "r"(base + 16));
            asm volatile("ld.shared.b32 %0, [%1];" : "=r"(a[mi][3]) : "r"(base + 8*RSB + 16));
        }
        #pragma unroll
        for (int nj = 0; nj < 4; nj++){
            uint32_t base = aB + nj*8*RSB + ks*32;
            asm volatile("ld.shared.b32 %0, [%1];" : "=r"(b[nj][0]) : "r"(base));
            asm volatile("ld.shared.b32 %0, [%1];" : "=r"(b[nj][1]) : "r"(base + 16));
        }
        #pragma unroll
        for (int mi = 0; mi < 4; mi++)
            #pragma unroll
            for (int nj = 0; nj < 4; nj++)
                MMA_H16(acc[mi][nj], a[mi], b[nj]);
    }
}

// ---------------- generic fp16 GEMM core (cp.async, ONE sync per chunk) ------
__device__ __forceinline__ void ldchunk(uint32_t sA, uint32_t sB,
    const __half* __restrict__ A, int lda, const __half* __restrict__ B, int ldb,
    int kt, int buf, int tid)
{
    const __half* Ak = A + kt*32;
    const __half* Bk = B + kt*32;
    #pragma unroll
    for (int r = 0; r < 2; r++){
        int t = tid + r*256;
        int row = t >> 2, seg = t & 3;
        uint32_t off = (uint32_t)(buf*TILEB + row*RSB + seg*16);
        asm volatile("cp.async.ca.shared.global [%0], [%1], 16;"
            :: "r"(sA + off), "l"(Ak + (size_t)row*lda + seg*8) : "memory");
        asm volatile("cp.async.ca.shared.global [%0], [%1], 16;"
            :: "r"(sB + off), "l"(Bk + (size_t)row*ldb + seg*8) : "memory");
    }
    asm volatile("cp.async.commit_group;" ::: "memory");
}

__device__ __forceinline__ void gemm_h16(
    const __half* __restrict__ A, int lda,
    const __half* __restrict__ B, int ldb,
    int K, uint8_t* smp, float acc[4][4][4])
{
    const int tid = threadIdx.x, lane = tid & 31, wid = tid >> 5;
    const int wm = wid & 1, wn = wid >> 1;
    uint32_t sA = smem_u32(smp), sB = sA + 2*TILEB;
    const int KT = K >> 5;

    ldchunk(sA, sB, A, lda, B, ldb, 0, 0, tid);
    for (int kt = 0; kt < KT; kt++){
        int buf = kt & 1;
        asm volatile("cp.async.wait_group 0;" ::: "memory");
        __syncthreads();
        if (kt + 1 < KT)
            ldchunk(sA, sB, A, lda, B, ldb, kt+1, buf^1, tid);
        compute_chunk(sA, sB, buf, lane, wm, wn, acc);
    }
}

#define GEMM_PROLOG                                            \
    __shared__ __align__(128) uint8_t sm[4*TILEB];             \
    const int lane = threadIdx.x & 31, wid = threadIdx.x >> 5; \
    float acc[4][4][4] = {};

// ---------------- prep kernels -----------------------------------------------
__global__ __launch_bounds__(256) void prep_w(
    const float* __restrict__ Wq, const float* __restrict__ bq,
    const float* __restrict__ Wk, const float* __restrict__ bk,
    const float* __restrict__ Wv, const float* __restrict__ bv)
{
    const float L2E = 1.44269504f;
    int i = blockIdx.x*256 + threadIdx.x;          // 65536 threads
    if (i < 32768) { g_Wqk[i] = __float2half_rn(Wq[i]*L2E); g_Wqk[32768 + i] = __float2half_rn(Wk[i]); }
    g_Wv[i] = __float2half_rn(Wv[i]);
    if (i < NB*NN) g_csum[i] = 0.f;                // zero colsum accumulators each replay
    if (i < 128) { g_bias[i] = bq[i]*L2E; g_bias[128 + i] = bk[i]; }
    if (i < 256) g_bias[256 + i] = bv[i];
}

__global__ __launch_bounds__(256) void prep_xT(const float* __restrict__ x)
{
    __shared__ float t[32][33];
    int b = blockIdx.z, m0 = blockIdx.x*32, c0 = blockIdx.y*32;
    int tx = threadIdx.x, ty = threadIdx.y;        // (32, 8)
    #pragma unroll
    for (int j = 0; j < 4; j++)
        t[ty + j*8][tx] = x[((size_t)b*CC + c0 + ty + j*8)*NN + m0 + tx];
    __syncthreads();
    #pragma unroll
    for (int j = 0; j < 4; j++)
        g_xT[((size_t)b*NN + m0 + ty + j*8)*CC + c0 + tx] = __float2half_rn(t[tx][ty + j*8]);
}

// ---------------- merged projection kernel -----------------------------------
__global__ __launch_bounds__(256, 2) void k_proj()
{
    GEMM_PROLOG
    int b = blockIdx.z, m0 = blockIdx.x*128;
    const __half* xb = g_xT + ((size_t)b*NN + m0)*CC;
    if (blockIdx.y < 2){
        int o0 = blockIdx.y*128;
        gemm_h16(xb, CC, g_Wqk + (size_t)o0*CC, CC, CC, sm, acc);
        int rb = m0 + (wid & 1)*64 + (lane >> 2);
        int cb = o0 + (wid >> 1)*32 + (lane & 3)*2;
        #pragma unroll
        for (int mi = 0; mi < 4; mi++)
            #pragma unroll
            for (int nj = 0; nj < 4; nj++){
                int r = rb + mi*16, c = cb + nj*8;
                float b0 = g_bias[c], b1 = g_bias[c + 1];
                __half* op = g_qk + ((size_t)b*NN + r)*CC + c;
                *reinterpret_cast<uint32_t*>(op)        = pack_h2_sat(acc[mi][nj][0] + b0, acc[mi][nj][1] + b1);
                *reinterpret_cast<uint32_t*>(op + 8*CC) = pack_h2_sat(acc[mi][nj][2] + b0, acc[mi][nj][3] + b1);
            }
    } else {
        int c0 = (blockIdx.y - 2)*128;
        gemm_h16(g_Wv + (size_t)c0*CC, CC, xb, CC, CC, sm, acc);
        int rb = c0 + (wid & 1)*64 + (lane >> 2);
        int cb = m0 + (wid >> 1)*32 + (lane & 3)*2;
        #pragma unroll
        for (int mi = 0; mi < 4; mi++)
            #pragma unroll
            for (int nj = 0; nj < 4; nj++){
                int r = rb + mi*16, c = cb + nj*8;
                float b0 = g_bias[256 + r], b1 = g_bias[256 + r + 8];
                __half* op = g_v + ((size_t)b*CC + r)*NN + c;
                *reinterpret_cast<uint32_t*>(op)        = pack_h2_sat(acc[mi][nj][0] + b0, acc[mi][nj][1] + b0);
                *reinterpret_cast<uint32_t*>(op + 8*NN) = pack_h2_sat(acc[mi][nj][2] + b1, acc[mi][nj][3] + b1);
            }
    }
}

// E[m][n] = 2^(q'[m].k[n]) = exp(q.k); fused per-column partial sums
__global__ __launch_bounds__(256, 2) void k_scores()
{
    GEMM_PROLOG
    int b = blockIdx.z, m0 = blockIdx.x*128, n0 = blockIdx.y*128;
    gemm_h16(g_qk + ((size_t)b*NN + m0)*CC, CC,
             g_qk + ((size_t)b*NN + n0)*CC + CQh, CC, CQh, sm, acc);
    int rb = m0 + (wid & 1)*64 + (lane >> 2);
    int cb = n0 + (wid >> 1)*32 + (lane & 3)*2;
    float cs[4][2];
    #pragma unroll
    for (int nj = 0; nj < 4; nj++){ cs[nj][0] = 0.f; cs[nj][1] = 0.f; }
    #pragma unroll
    for (int mi = 0; mi < 4; mi++)
        #pragma unroll
        for (int nj = 0; nj < 4; nj++){
            float e0 = fexp2(acc[mi][nj][0]), e1 = fexp2(acc[mi][nj][1]);
            float e2 = fexp2(acc[mi][nj][2]), e3 = fexp2(acc[mi][nj][3]);
            cs[nj][0] += e0 + e2;
            cs[nj][1] += e1 + e3;
            int r = rb + mi*16, c = cb + nj*8;
            __half* op = g_E + ((size_t)b*NN + r)*NN + c;
            *reinterpret_cast<uint32_t*>(op)        = pack_h2_sat(e0, e1);
            *reinterpret_cast<uint32_t*>(op + 8*NN) = pack_h2_sat(e2, e3);
        }
    #pragma unroll
    for (int nj = 0; nj < 4; nj++)
        #pragma unroll
        for (int j = 0; j < 2; j++){
            float v = cs[nj][j];
            v += __shfl_down_sync(0xFFFFFFFFu, v, 4);
            v += __shfl_down_sync(0xFFFFFFFFu, v, 8);
            v += __shfl_down_sync(0xFFFFFFFFu, v, 16);
            cs[nj][j] = v;
        }
    if (lane < 4){
        #pragma unroll
        for (int nj = 0; nj < 4; nj++)
            #pragma unroll
            for (int j = 0; j < 2; j++)
                atomicAdd(&g_csum[b*NN + n0 + (wid >> 1)*32 + lane*2 + nj*8 + j], cs[nj][j]);
    }
}

__global__ __launch_bounds__(256) void k_rcp()
{
    int i = blockIdx.x*256 + threadIdx.x;          // < NB*NN
    g_rcph[i] = __float2half_rn(256.0f / g_csum[i]);
}

// v'[c][m] = v[c][m] * rcp_h[m]  (in place; k_proj rewrites g_v each replay)
__global__ __launch_bounds__(256) void k_vscale()
{
    size_t i = ((size_t)blockIdx.x*256 + threadIdx.x)*8;   // halves index
    int m = (int)(i & (NN - 1));
    int b = (int)(i >> 20);                                 // CC*NN = 2^20 per batch
    uint4 v  = *reinterpret_cast<uint4*>(g_v + i);
    uint4 rc = *reinterpret_cast<const uint4*>(g_rcph + b*NN + m);
    __half2* hv = reinterpret_cast<__half2*>(&v);
    const __half2* hr = reinterpret_cast<const __half2*>(&rc);
    hv[0] = __hmul2(hv[0], hr[0]);
    hv[1] = __hmul2(hv[1], hr[1]);
    hv[2] = __hmul2(hv[2], hr[2]);
    hv[3] = __hmul2(hv[3], hr[3]);
    *reinterpret_cast<uint4*>(g_v + i) = v;
}

// ---------------- output GEMM: vanilla (rcp folded into v) -------------------
// out[c][m] = sum_n v'[c][n] * E[m][n];  y = (gamma/256)*out + x
__global__ __launch_bounds__(256, 2) void k_out(
    const float* __restrict__ x, const float* __restrict__ gamma, float* __restrict__ y)
{
    GEMM_PROLOG
    int b = blockIdx.z, m0 = blockIdx.x*128, c0 = blockIdx.y*128;
    gemm_h16(g_v + ((size_t)b*CC + c0)*NN, NN,
             g_E + ((size_t)b*NN + m0)*NN, NN, NN, sm, acc);
    float gm = gamma[0] * 0.00390625f;   // /256 compensates rcp_h scaling
    int rb = c0 + (wid & 1)*64 + (lane >> 2);
    int cb = m0 + (wid >> 1)*32 + (lane & 3)*2;
    #pragma unroll
    for (int mi = 0; mi < 4; mi++)
        #pragma unroll
        for (int nj = 0; nj < 4; nj++){
            int r = rb + mi*16, c = cb + nj*8;
            size_t p0 = ((size_t)b*CC + r)*NN + c;
            size_t p1 = p0 + (size_t)8*NN;
            float2 x0 = *reinterpret_cast<const float2*>(x + p0);
            float2 x1 = *reinterpret_cast<const float2*>(x + p1);
            *reinterpret_cast<float2*>(y + p0) =
                make_float2(fmaf(gm, acc[mi][nj][0], x0.x), fmaf(gm, acc[mi][nj][1], x0.y));
            *reinterpret_cast<float2*>(y + p1) =
                make_float2(fmaf(gm, acc[mi][nj][2], x1.x), fmaf(gm, acc[mi][nj][3], x1.y));
        }
}

// ---------------- launcher ---------------------------------------------------
extern "C" void kernel_launch(void* const* d_in, const int* in_sizes, int n_in,
                              void* d_out, int out_size)
{
    const float* x     = (const float*)d_in[0];
    const float* Wq    = (const float*)d_in[1];
    const float* bq    = (const float*)d_in[2];
    const float* Wk    = (const float*)d_in[3];
    const float* bk    = (const float*)d_in[4];
    const float* Wv    = (const float*)d_in[5];
    const float* bv    = (const float*)d_in[6];
    const float* gamma = (const float*)d_in[7];
    float* y = (float*)d_out;

    prep_w  <<<256, 256>>>(Wq, bq, Wk, bk, Wv, bv);
    prep_xT <<<dim3(NN/32, CC/32, NB), dim3(32, 8)>>>(x);
    k_proj  <<<dim3(NN/128, 4, NB), 256>>>();
    k_scores<<<dim3(NN/128, NN/128, NB), 256>>>();
    k_rcp   <<<NB*NN/256, 256>>>();
    k_vscale<<<NB*CC*NN/(256*8), 256>>>();
    k_out   <<<dim3(NN/128, CC/128, NB), 256>>>(x, gamma, y);
}

// round 15
// speedup vs baseline: 1.6172x; 1.0114x over previous
#include <cuda_runtime.h>
#include <cuda_fp16.h>
#include <cstdint>

#define NB 8
#define CC 256
#define CQh 128
#define NN 4096
#define RSB 80          // smem row stride bytes -> conflict-free fragment LDS
#define TILEB 10240     // 128 rows * 80B

// ---------------- scratch (device globals) ----------------------------------
__device__ __half g_xT [(size_t)NB*NN*CC];     // [b][m][c]
__device__ __half g_qk [(size_t)NB*NN*CC];     // [b][m][o] o<128: q*log2e, else k
__device__ __half g_v  [(size_t)NB*CC*NN];     // [b][c][m]; scaled by rcp_h in k_vscale
__device__ __half g_E  [(size_t)NB*NN*NN];     // [b][m][n] = exp(S)  268MB
__device__ float  g_csum[NB*NN];               // column sums (atomic)
__device__ __half g_rcph[NB*NN];               // fp16(256/colsum)
__device__ __half g_Wqk[2*CQh*CC];
__device__ __half g_Wv [CC*CC];
__device__ float  g_bias[512];                 // q:0-127 (x log2e) k:128-255 v:256-511

// ---------------- helpers ----------------------------------------------------
__device__ __forceinline__ uint32_t smem_u32(const void* p){
    uint32_t a;
    asm("{ .reg .u64 t; cvta.to.shared.u64 t, %1; cvt.u32.u64 %0, t; }" : "=r"(a) : "l"(p));
    return a;
}
// fma-pipe 2^t (scores pre-scaled by log2e); degree-5, rel err ~1.6e-4
__device__ __forceinline__ float fexp2(float t){
    t = fmaxf(t, -80.f);
    float fi = floorf(t);
    float f = t - fi;
    float p = 1.33335581e-3f;
    p = fmaf(p, f, 9.61812911e-3f);
    p = fmaf(p, f, 5.55041087e-2f);
    p = fmaf(p, f, 2.40226507e-1f);
    p = fmaf(p, f, 6.93147181e-1f);
    p = fmaf(p, f, 1.0f);
    return __int_as_float(__float_as_int(p) + ((int)fi << 23));
}
__device__ __forceinline__ uint32_t pack_h2_sat(float lo, float hi){
    uint32_t r;
    asm("cvt.rn.satfinite.f16x2.f32 %0, %1, %2;" : "=r"(r) : "f"(hi), "f"(lo));
    return r;
}

#define MMA_H16(acc, a, b)                                                     \
    asm volatile("mma.sync.aligned.m16n8k16.row.col.f32.f16.f16.f32 "          \
        "{%0,%1,%2,%3}, {%4,%5,%6,%7}, {%8,%9}, {%0,%1,%2,%3};"                \
        : "+f"((acc)[0]), "+f"((acc)[1]), "+f"((acc)[2]), "+f"((acc)[3])       \
        : "r"((a)[0]), "r"((a)[1]), "r"((a)[2]), "r"((a)[3]),                  \
          "r"((b)[0]), "r"((b)[1]))

// ---------------- fragment compute (one 32-deep K chunk, scalar LDS) ---------
__device__ __forceinline__ void compute_chunk(uint32_t sA, uint32_t sB, int buf,
                                              int lane, int wm, int wn, float acc[4][4][4])
{
    uint32_t aA = sA + buf*TILEB + (wm*64 + (lane>>2))*RSB + (lane&3)*4;
    uint32_t aB = sB + buf*TILEB + (wn*32 + (lane>>2))*RSB + (lane&3)*4;
    #pragma unroll
    for (int ks = 0; ks < 2; ks++){
        uint32_t a[4][4], b[4][2];
        #pragma unroll
        for (int mi = 0; mi < 4; mi++){
            uint32_t base = aA + mi*16*RSB + ks*32;
            asm volatile("ld.shared.b32 %0, [%1];" : "=r"(a[mi][0]) : "r"(base));
            asm volatile("ld.shared.b32 %0, [%1];" : "=r"(a[mi][1]) : "r"(base + 8*RSB));
            asm volatile("ld.shared.b32 %0, [%1];" : "=r"(a[mi][2]) : "r"(base + 16));
            asm volatile("ld.shared.b32 %0, [%1];" : "=r"(a[mi][3]) : "r"(base + 8*RSB + 16));
        }
        #pragma unroll
        for (int nj = 0; nj < 4; nj++){
            uint32_t base = aB + nj*8*RSB + ks*32;
            asm volatile("ld.shared.b32 %0, [%1];" : "=r"(b[nj][0]) : "r"(base));
            asm volatile("ld.shared.b32 %0, [%1];" : "=r"(b[nj][1]) : "r"(base + 16));
        }
        #pragma unroll
        for (int mi = 0; mi < 4; mi++)
            #pragma unroll
            for (int nj = 0; nj < 4; nj++)
                MMA_H16(acc[mi][nj], a[mi], b[nj]);
    }
}

// ---------------- generic fp16 GEMM core (cp.async.cg, ONE sync per chunk) ---
__device__ __forceinline__ void ldchunk(uint32_t sA, uint32_t sB,
    const __half* __restrict__ A, int lda, const __half* __restrict__ B, int ldb,
    int kt, int buf, int tid)
{
    const __half* Ak = A + kt*32;
    const __half* Bk = B + kt*32;
    #pragma unroll
    for (int r = 0; r < 2; r++){
        int t = tid + r*256;
        int row = t >> 2, seg = t & 3;
        uint32_t off = (uint32_t)(buf*TILEB + row*RSB + seg*16);
        asm volatile("cp.async.cg.shared.global [%0], [%1], 16;"
            :: "r"(sA + off), "l"(Ak + (size_t)row*lda + seg*8) : "memory");
        asm volatile("cp.async.cg.shared.global [%0], [%1], 16;"
            :: "r"(sB + off), "l"(Bk + (size_t)row*ldb + seg*8) : "memory");
    }
    asm volatile("cp.async.commit_group;" ::: "memory");
}

__device__ __forceinline__ void gemm_h16(
    const __half* __restrict__ A, int lda,
    const __half* __restrict__ B, int ldb,
    int K, uint8_t* smp, float acc[4][4][4])
{
    const int tid = threadIdx.x, lane = tid & 31, wid = tid >> 5;
    const int wm = wid & 1, wn = wid >> 1;
    uint32_t sA = smem_u32(smp), sB = sA + 2*TILEB;
    const int KT = K >> 5;

    ldchunk(sA, sB, A, lda, B, ldb, 0, 0, tid);
    for (int kt = 0; kt < KT; kt++){
        int buf = kt & 1;
        asm volatile("cp.async.wait_group 0;" ::: "memory");
        __syncthreads();
        if (kt + 1 < KT)
            ldchunk(sA, sB, A, lda, B, ldb, kt+1, buf^1, tid);
        compute_chunk(sA, sB, buf, lane, wm, wn, acc);
    }
}

#define GEMM_PROLOG                                            \
    __shared__ __align__(128) uint8_t sm[4*TILEB];             \
    const int lane = threadIdx.x & 31, wid = threadIdx.x >> 5; \
    float acc[4][4][4] = {};

// ---------------- prep kernels -----------------------------------------------
__global__ __launch_bounds__(256) void prep_w(
    const float* __restrict__ Wq, const float* __restrict__ bq,
    const float* __restrict__ Wk, const float* __restrict__ bk,
    const float* __restrict__ Wv, const float* __restrict__ bv)
{
    const float L2E = 1.44269504f;
    int i = blockIdx.x*256 + threadIdx.x;          // 65536 threads
    if (i < 32768) { g_Wqk[i] = __float2half_rn(Wq[i]*L2E); g_Wqk[32768 + i] = __float2half_rn(Wk[i]); }
    g_Wv[i] = __float2half_rn(Wv[i]);
    if (i < NB*NN) g_csum[i] = 0.f;                // zero colsum accumulators each replay
    if (i < 128) { g_bias[i] = bq[i]*L2E; g_bias[128 + i] = bk[i]; }
    if (i < 256) g_bias[256 + i] = bv[i];
}

__global__ __launch_bounds__(256) void prep_xT(const float* __restrict__ x)
{
    __shared__ float t[32][33];
    int b = blockIdx.z, m0 = blockIdx.x*32, c0 = blockIdx.y*32;
    int tx = threadIdx.x, ty = threadIdx.y;        // (32, 8)
    #pragma unroll
    for (int j = 0; j < 4; j++)
        t[ty + j*8][tx] = x[((size_t)b*CC + c0 + ty + j*8)*NN + m0 + tx];
    __syncthreads();
    #pragma unroll
    for (int j = 0; j < 4; j++)
        g_xT[((size_t)b*NN + m0 + ty + j*8)*CC + c0 + tx] = __float2half_rn(t[tx][ty + j*8]);
}

// ---------------- merged projection kernel -----------------------------------
__global__ __launch_bounds__(256, 2) void k_proj()
{
    GEMM_PROLOG
    int b = blockIdx.z, m0 = blockIdx.x*128;
    const __half* xb = g_xT + ((size_t)b*NN + m0)*CC;
    if (blockIdx.y < 2){
        int o0 = blockIdx.y*128;
        gemm_h16(xb, CC, g_Wqk + (size_t)o0*CC, CC, CC, sm, acc);
        int rb = m0 + (wid & 1)*64 + (lane >> 2);
        int cb = o0 + (wid >> 1)*32 + (lane & 3)*2;
        #pragma unroll
        for (int mi = 0; mi < 4; mi++)
            #pragma unroll
            for (int nj = 0; nj < 4; nj++){
                int r = rb + mi*16, c = cb + nj*8;
                float b0 = g_bias[c], b1 = g_bias[c + 1];
                __half* op = g_qk + ((size_t)b*NN + r)*CC + c;
                *reinterpret_cast<uint32_t*>(op)        = pack_h2_sat(acc[mi][nj][0] + b0, acc[mi][nj][1] + b1);
                *reinterpret_cast<uint32_t*>(op + 8*CC) = pack_h2_sat(acc[mi][nj][2] + b0, acc[mi][nj][3] + b1);
            }
    } else {
        int c0 = (blockIdx.y - 2)*128;
        gemm_h16(g_Wv + (size_t)c0*CC, CC, xb, CC, CC, sm, acc);
        int rb = c0 + (wid & 1)*64 + (lane >> 2);
        int cb = m0 + (wid >> 1)*32 + (lane & 3)*2;
        #pragma unroll
        for (int mi = 0; mi < 4; mi++)
            #pragma unroll
            for (int nj = 0; nj < 4; nj++){
                int r = rb + mi*16, c = cb + nj*8;
                float b0 = g_bias[256 + r], b1 = g_bias[256 + r + 8];
                __half* op = g_v + ((size_t)b*CC + r)*NN + c;
                *reinterpret_cast<uint32_t*>(op)        = pack_h2_sat(acc[mi][nj][0] + b0, acc[mi][nj][1] + b0);
                *reinterpret_cast<uint32_t*>(op + 8*NN) = pack_h2_sat(acc[mi][nj][2] + b1, acc[mi][nj][3] + b1);
            }
    }
}

// E[m][n] = 2^(q'[m].k[n]) = exp(q.k); fused per-column partial sums (half2)
__global__ __launch_bounds__(256, 2) void k_scores()
{
    GEMM_PROLOG
    int b = blockIdx.z, m0 = blockIdx.x*128, n0 = blockIdx.y*128;
    gemm_h16(g_qk + ((size_t)b*NN + m0)*CC, CC,
             g_qk + ((size_t)b*NN + n0)*CC + CQh, CC, CQh, sm, acc);
    int rb = m0 + (wid & 1)*64 + (lane >> 2);
    int cb = n0 + (wid >> 1)*32 + (lane & 3)*2;
    __half2 csh[4];
    #pragma unroll
    for (int nj = 0; nj < 4; nj++) csh[nj] = __half2(__float2half(0.f), __float2half(0.f));
    #pragma unroll
    for (int mi = 0; mi < 4; mi++)
        #pragma unroll
        for (int nj = 0; nj < 4; nj++){
            float e0 = fexp2(acc[mi][nj][0]), e1 = fexp2(acc[mi][nj][1]);
            float e2 = fexp2(acc[mi][nj][2]), e3 = fexp2(acc[mi][nj][3]);
            uint32_t pk0 = pack_h2_sat(e0, e1);
            uint32_t pk1 = pack_h2_sat(e2, e3);
            csh[nj] = __hadd2(csh[nj], *reinterpret_cast<__half2*>(&pk0));
            csh[nj] = __hadd2(csh[nj], *reinterpret_cast<__half2*>(&pk1));
            int r = rb + mi*16, c = cb + nj*8;
            __half* op = g_E + ((size_t)b*NN + r)*NN + c;
            *reinterpret_cast<uint32_t*>(op)        = pk0;
            *reinterpret_cast<uint32_t*>(op + 8*NN) = pk1;
        }
    // reduce across the 8 lanes sharing each column (lane>>2 axis)
    float cs[4][2];
    #pragma unroll
    for (int nj = 0; nj < 4; nj++){
        cs[nj][0] = __low2float(csh[nj]);
        cs[nj][1] = __high2float(csh[nj]);
        #pragma unroll
        for (int j = 0; j < 2; j++){
            float v = cs[nj][j];
            v += __shfl_down_sync(0xFFFFFFFFu, v, 4);
            v += __shfl_down_sync(0xFFFFFFFFu, v, 8);
            v += __shfl_down_sync(0xFFFFFFFFu, v, 16);
            cs[nj][j] = v;
        }
    }
    if (lane < 4){
        #pragma unroll
        for (int nj = 0; nj < 4; nj++)
            #pragma unroll
            for (int j = 0; j < 2; j++)
                atomicAdd(&g_csum[b*NN + n0 + (wid >> 1)*32 + lane*2 + nj*8 + j], cs[nj][j]);
    }
}

__global__ __launch_bounds__(256) void k_rcp()
{
    int i = blockIdx.x*256 + threadIdx.x;          // < NB*NN
    g_rcph[i] = __float2half_rn(256.0f / g_csum[i]);
}

// v'[c][m] = v[c][m] * rcp_h[m]  (in place; k_proj rewrites g_v each replay)
__global__ __launch_bounds__(256) void k_vscale()
{
    size_t i = ((size_t)blockIdx.x*256 + threadIdx.x)*8;   // halves index
    int m = (int)(i & (NN - 1));
    int b = (int)(i >> 20);                                 // CC*NN = 2^20 per batch
    uint4 v  = *reinterpret_cast<uint4*>(g_v + i);
    uint4 rc = *reinterpret_cast<const uint4*>(g_rcph + b*NN + m);
    __half2* hv = reinterpret_cast<__half2*>(&v);
    const __half2* hr = reinterpret_cast<const __half2*>(&rc);
    hv[0] = __hmul2(hv[0], hr[0]);
    hv[1] = __hmul2(hv[1], hr[1]);
    hv[2] = __hmul2(hv[2], hr[2]);
    hv[3] = __hmul2(hv[3], hr[3]);
    *reinterpret_cast<uint4*>(g_v + i) = v;
}

// ---------------- output GEMM: vanilla (rcp folded into v) -------------------
// out[c][m] = sum_n v'[c][n] * E[m][n];  y = (gamma/256)*out + x
__global__ __launch_bounds__(256, 2) void k_out(
    const float* __restrict__ x, const float* __restrict__ gamma, float* __restrict__ y)
{
    GEMM_PROLOG
    int b = blockIdx.z, m0 = blockIdx.x*128, c0 = blockIdx.y*128;
    gemm_h16(g_v + ((size_t)b*CC + c0)*NN, NN,
             g_E + ((size_t)b*NN + m0)*NN, NN, NN, sm, acc);
    float gm = gamma[0] * 0.00390625f;   // /256 compensates rcp_h scaling
    int rb = c0 + (wid & 1)*64 + (lane >> 2);
    int cb = m0 + (wid >> 1)*32 + (lane & 3)*2;
    #pragma unroll
    for (int mi = 0; mi < 4; mi++)
        #pragma unroll
        for (int nj = 0; nj < 4; nj++){
            int r = rb + mi*16, c = cb + nj*8;
            size_t p0 = ((size_t)b*CC + r)*NN + c;
            size_t p1 = p0 + (size_t)8*NN;
            float2 x0 = *reinterpret_cast<const float2*>(x + p0);
            float2 x1 = *reinterpret_cast<const float2*>(x + p1);
            *reinterpret_cast<float2*>(y + p0) =
                make_float2(fmaf(gm, acc[mi][nj][0], x0.x), fmaf(gm, acc[mi][nj][1], x0.y));
            *reinterpret_cast<float2*>(y + p1) =
                make_float2(fmaf(gm, acc[mi][nj][2], x1.x), fmaf(gm, acc[mi][nj][3], x1.y));
        }
}

// ---------------- launcher ---------------------------------------------------
extern "C" void kernel_launch(void* const* d_in, const int* in_sizes, int n_in,
                              void* d_out, int out_size)
{
    const float* x     = (const float*)d_in[0];
    const float* Wq    = (const float*)d_in[1];
    const float* bq    = (const float*)d_in[2];
    const float* Wk    = (const float*)d_in[3];
    const float* bk    = (const float*)d_in[4];
    const float* Wv    = (const float*)d_in[5];
    const float* bv    = (const float*)d_in[6];
    const float* gamma = (const float*)d_in[7];
    float* y = (float*)d_out;

    prep_w  <<<256, 256>>>(Wq, bq, Wk, bk, Wv, bv);
    prep_xT <<<dim3(NN/32, CC/32, NB), dim3(32, 8)>>>(x);
    k_proj  <<<dim3(NN/128, 4, NB), 256>>>();
    k_scores<<<dim3(NN/128, NN/128, NB), 256>>>();
    k_rcp   <<<NB*NN/256, 256>>>();
    k_vscale<<<NB*CC*NN/(256*8), 256>>>();
    k_out   <<<dim3(NN/128, CC/128, NB), 256>>>(x, gamma, y);
}